// round 5
// baseline (speedup 1.0000x reference)
#include <cuda_runtime.h>
#include <cstddef>

// Problem shape (fixed by the dataset):
//   feature_maps: (32, 256, 64, 64) f32   -> d_in[0]
//   anchors:      (32, 2048, 2)    f32    -> d_in[1]
//   out:          (32, 2048, 256)  f32
#define NB      32
#define NC      256
#define HH      64
#define HWSZ    4096          // 64*64
#define NANCH   2048
#define CPB     4             // channels interleaved per float4 plane
#define THREADS 512

__global__ __launch_bounds__(THREADS, 2)
void interp_gather_kernel(const float* __restrict__ fm,
                          const float* __restrict__ anchors,
                          float* __restrict__ out)
{
    // One buffer of 4096 float4: smem4[pixel] = {c0, c0+1, c0+2, c0+3}[pixel]
    extern __shared__ float4 smem4[];          // 4096 * 16B = 65536 B

    const int tid = threadIdx.x;
    const int b   = blockIdx.y;
    const int c0  = blockIdx.x * CPB;

    // ---- Transpose 4 planar channels into float4-interleaved SMEM ----
    // Warp: c = lane&3, pixels consecutive per c -> gmem side is 4 full 32B
    // segments per warp access; smem side is consecutive 4B lanes (no conflict).
    {
        const int c_lane = tid & 3;
        const int p0     = tid >> 2;           // 0..127
        const float* src = fm + ((size_t)b * NC + c0 + c_lane) * HWSZ + p0;
        float* dst = (float*)smem4 + 4 * p0 + c_lane;
        #pragma unroll 8
        for (int k = 0; k < HWSZ / (THREADS / CPB); k++) {   // 32 iters
            dst[k * 128 * 4] = src[k * 128];
        }
    }

    const float2* anc = (const float2*)(anchors + (size_t)b * NANCH * 2);
    __syncthreads();

    // ---- Gather + blend: one anchor x 4 channels per thread-iteration ----
    float* op = out + (size_t)b * NANCH * NC + c0;

    #pragma unroll
    for (int k = 0; k < NANCH / THREADS; k++) {              // 4 iters
        int n = tid + k * THREADS;
        float2 a = anc[n];
        float px = fminf(fmaxf(a.x * 63.0f, 0.0f), 63.0f);
        float py = fminf(fmaxf(a.y * 63.0f, 0.0f), 63.0f);
        float fx = floorf(px), fy = floorf(py);
        int ix = (int)fx, iy = (int)fy;
        int dxi = (int)ceilf(px) - ix;                       // 0 or 1
        int dyi = ((int)ceilf(py) - iy) << 6;                // 0 or 64
        float dx = px - fx, dy = py - fy;
        int i00 = iy * HH + ix;

        float4 v00 = smem4[i00];
        float4 v01 = smem4[i00 + dxi];
        float4 v10 = smem4[i00 + dyi];
        float4 v11 = smem4[i00 + dyi + dxi];

        // exact reference blend order, per channel component
        float4 r;
        float tt, bb;
        tt = v00.x + (v01.x - v00.x) * dx;
        bb = v10.x + (v11.x - v10.x) * dx;
        r.x = tt + (bb - tt) * dy;
        tt = v00.y + (v01.y - v00.y) * dx;
        bb = v10.y + (v11.y - v10.y) * dx;
        r.y = tt + (bb - tt) * dy;
        tt = v00.z + (v01.z - v00.z) * dx;
        bb = v10.z + (v11.z - v10.z) * dx;
        r.z = tt + (bb - tt) * dy;
        tt = v00.w + (v01.w - v00.w) * dx;
        bb = v10.w + (v11.w - v10.w) * dx;
        r.w = tt + (bb - tt) * dy;

        *(float4*)(op + (size_t)n * NC) = r;
    }
}

extern "C" void kernel_launch(void* const* d_in, const int* in_sizes, int n_in,
                              void* d_out, int out_size)
{
    const float* fm  = (const float*)d_in[0];
    const float* anc = (const float*)d_in[1];
    float* out       = (float*)d_out;

    const size_t smem_bytes = (size_t)HWSZ * sizeof(float4);   // 65536 B

    cudaFuncSetAttribute(interp_gather_kernel,
                         cudaFuncAttributeMaxDynamicSharedMemorySize,
                         (int)smem_bytes);

    dim3 grid(NC / CPB, NB);   // (64, 32) = 2048 blocks
    interp_gather_kernel<<<grid, THREADS, smem_bytes>>>(fm, anc, out);
}